// round 1
// baseline (speedup 1.0000x reference)
#include <cuda_runtime.h>

// QLSTM collapsed analytically:
//   quantum_gate(comb, p)[:, k] = prod_{j<=k} cos(p_j) * cos(comb_j)
// Only k < H=4 used and comb[0:4] = x  => gates depend only on x_t.
// Recurrence per (b,k):  c_t = f_t * c_{t-1} + i_t * g_t ;  h_t = o_t * tanh(c_t)
// with f=sig(AF_k*P), i=sig(AI_k*P), g=tanh(AG_k*P), o=sig(AO_k*P),
//   P_k(t,b) = prod_{j<=k} cos(x[t,b,j]),  A*_k = prod_{j<=k} cos(p*_j).
// Parallel scan over T: 8 chunks of 16 steps, warp = one batch element,
// lane = (chunk, k). Affine chunk maps composed by shuffle scan.

#define T_STEPS 128
#define BATCH   4096
#define HID     4
#define CHUNK   16
#define NCHUNK  8
#define FULLMASK 0xffffffffu

__device__ __forceinline__ float fast_sigmoid(float z) {
    // 1 / (1 + e^{-z});  __expf + __fdividef: ~2ulp each
    return __fdividef(1.0f, 1.0f + __expf(-z));
}
__device__ __forceinline__ float fast_tanh(float z) {
    // 1 - 2/(e^{2z}+1); handles +-inf of exp correctly
    return 1.0f - __fdividef(2.0f, __expf(2.0f * z) + 1.0f);
}

__global__ void __launch_bounds__(256) qlstm_kernel(
    const float* __restrict__ inp,   // [T, B, 4]
    const float* __restrict__ prm_f, // [8]
    const float* __restrict__ prm_i,
    const float* __restrict__ prm_g,
    const float* __restrict__ prm_o,
    float* __restrict__ out)         // [T*B*H + B*H + B*H]
{
    const int warp_id = (blockIdx.x * blockDim.x + threadIdx.x) >> 5;
    if (warp_id >= BATCH) return;
    const int b     = warp_id;
    const int lane  = threadIdx.x & 31;
    const int k     = lane & 3;        // hidden index 0..3
    const int chunk = lane >> 2;       // time chunk 0..7

    // --- per-k parameter prefix products: A_k = prod_{j<=k} cos(p_j) ---
    float AF = 1.0f, AI = 1.0f, AG = 1.0f, AO = 1.0f;
#pragma unroll
    for (int j = 0; j < HID; ++j) {
        if (j <= k) {
            AF *= __cosf(prm_f[j]);
            AI *= __cosf(prm_i[j]);
            AG *= __cosf(prm_g[j]);
            AO *= __cosf(prm_o[j]);
        }
    }

    // --- phase 1: chunk-local gates + affine scan (c0, prod f) ---
    float o_arr[CHUNK];
    float c0_arr[CHUNK];
    float pf_arr[CHUNK];

    float c_loc = 0.0f;   // chunk-local c starting from 0
    float pf    = 1.0f;   // running product of f within chunk

    const float4* __restrict__ xin = (const float4*)inp;
    const int t0 = chunk * CHUNK;

#pragma unroll
    for (int it = 0; it < CHUNK; ++it) {
        const int t = t0 + it;
        float4 x4 = xin[t * BATCH + b];
        float xk = (k == 0) ? x4.x : (k == 1) ? x4.y : (k == 2) ? x4.z : x4.w;

        // segmented (groups of 4) inclusive prefix product of cos(x_j)
        float P = __cosf(xk);
        float s1 = __shfl_up_sync(FULLMASK, P, 1);
        if (k >= 1) P *= s1;
        float s2 = __shfl_up_sync(FULLMASK, P, 2);
        if (k >= 2) P *= s2;

        float f = fast_sigmoid(AF * P);
        float i = fast_sigmoid(AI * P);
        float g = fast_tanh   (AG * P);
        float o = fast_sigmoid(AO * P);

        c_loc = __fmaf_rn(f, c_loc, i * g);
        pf    = pf * f;

        o_arr[it]  = o;
        c0_arr[it] = c_loc;
        pf_arr[it] = pf;
    }

    // --- phase 2: warp scan over 8 chunks (stride-4 lanes share k) ---
    // affine map: c_out = C + F * c_in ; compose left-to-right
    float F = pf, C = c_loc;
#pragma unroll
    for (int off = 4; off <= 16; off <<= 1) {
        float Fo = __shfl_up_sync(FULLMASK, F, off);
        float Co = __shfl_up_sync(FULLMASK, C, off);
        if (lane >= off) {
            C = __fmaf_rn(F, Co, C);
            F = F * Fo;
        }
    }
    // c entering this chunk = inclusive result of previous chunk (0 for chunk 0)
    float cin = __shfl_up_sync(FULLMASK, C, 4);
    if (chunk == 0) cin = 0.0f;

    // --- phase 3: reconstruct c_t, emit h_t ---
    const int bk = b * HID + k;
#pragma unroll
    for (int it = 0; it < CHUNK; ++it) {
        const int t = t0 + it;
        float ct = __fmaf_rn(pf_arr[it], cin, c0_arr[it]);
        float h  = o_arr[it] * fast_tanh(ct);
        out[t * (BATCH * HID) + bk] = h;
        if (chunk == NCHUNK - 1 && it == CHUNK - 1) {
            // hx = last h, cx = last c
            out[T_STEPS * BATCH * HID + bk] = h;
            out[T_STEPS * BATCH * HID + BATCH * HID + bk] = ct;
        }
    }
}

extern "C" void kernel_launch(void* const* d_in, const int* in_sizes, int n_in,
                              void* d_out, int out_size) {
    (void)in_sizes; (void)n_in; (void)out_size;
    const float* inp   = (const float*)d_in[0];
    const float* prm_f = (const float*)d_in[1];
    const float* prm_i = (const float*)d_in[2];
    const float* prm_g = (const float*)d_in[3];
    const float* prm_o = (const float*)d_in[4];
    float* out = (float*)d_out;

    // 4096 warps (one per batch element), 8 warps per block
    qlstm_kernel<<<BATCH / 8, 256>>>(inp, prm_f, prm_i, prm_g, prm_o, out);
}